// round 9
// baseline (speedup 1.0000x reference)
#include <cuda_runtime.h>
#include <math.h>

#define Bsz 256
#define Hsz 512
#define Isz 512

// ---------------- scratch (device globals, no allocation) ----------------
__device__ float g_partial[4 * 4 * Bsz * Hsz]; // [z][gate][b][k] GEMM K-split partials (8 MB)
__device__ float g_hbp[4 * Bsz * Hsz];         // [z][b][k] hebb-dot h-split partials (2 MB)
__device__ float g_itc[Bsz * Hsz];             // inputstocell
__device__ float g_eta[Bsz];                   // tanh(hactiv @ Wmod.T + bmod)

// ---------------------------------------------------------------------------
// Fused kernel 1: gate GEMMs + hebb contraction, block-range dispatched.
//
// GEMM blocks (512, bid%3==0): one gate per block, 64x64 tile, 128-k slab,
//   128 threads, 8x4 microtile -> 0.67 FMA/LDS-byte (was 0.5) so the smem
//   crossbar is no longer co-limiting with the FMA pipe.
// HEBBDOT blocks (1024): stream hebb once (268 MB); 128 threads, 128-row
//   h slab each, float4 per thread over k.
//
// Interleave 1:2; __launch_bounds__(128,6) -> 6 blocks/SM (~2 gemm + 4 hebb),
// 512 streaming threads/SM with lighter issue/L1 interference.
// ---------------------------------------------------------------------------
#define N_GEMMB 512
#define N_HEBBB 1024
#define GRID_FUSED (N_GEMMB + N_HEBBB)   // 1536

__global__ __launch_bounds__(128, 6) void fused_gemm_hebbdot(
    const float* __restrict__ x, const float* __restrict__ h0,
    const float* __restrict__ Wxf, const float* __restrict__ Wxi,
    const float* __restrict__ Wxo, const float* __restrict__ Wxc,
    const float* __restrict__ Whf, const float* __restrict__ Whi,
    const float* __restrict__ Who, const float* __restrict__ w,
    const float* __restrict__ hebb)
{
    // union smem: gemm needs 4*16*68 floats = 17408 B; hebbdot needs 512 B
    __shared__ float smem[4 * 16 * 68];

    const int bid = blockIdx.x;
    const int tid = threadIdx.x;

    if (bid % 3 != 0) {
        // ---------------- hebbdot path ----------------
        const int hid = bid - bid / 3 - 1;         // 0..1023
        const int b  = hid >> 2;
        const int hz = hid & 3;                    // 128-row slab of h

        float* sh = smem;                          // 128 floats
        sh[tid] = h0[b * Hsz + hz * 128 + tid];
        __syncthreads();

        const float4* hp = (const float4*)(hebb + (size_t)b * Hsz * Hsz
                                                + (size_t)(hz * 128) * Hsz) + tid;
        float4 acc = {0.f, 0.f, 0.f, 0.f};
#pragma unroll 8
        for (int h = 0; h < 128; h++) {
            const float4 v = __ldcs(&hp[(size_t)h * 128]);
            const float s = sh[h];
            acc.x += s * v.x; acc.y += s * v.y; acc.z += s * v.z; acc.w += s * v.w;
        }
        ((float4*)(g_hbp + (hz * Bsz + b) * Hsz))[tid] = acc;
        return;
    }

    // ---------------- gemm path ----------------
    const int gid = bid / 3;                       // 0..511
    const int g  = gid & 3;                        // gate
    const int nx = (gid >> 2) & 7;                 // 8 n-tiles
    const int ny = (gid >> 5) & 3;                 // 4 m-tiles
    const int z  = gid >> 7;                       // 4 k-slabs

    float (*sAx)[68] = (float (*)[68])(smem);                 // [16][68]
    float (*sAh)[68] = (float (*)[68])(smem + 16 * 68);
    float (*sBx)[68] = (float (*)[68])(smem + 2 * 16 * 68);
    float (*sBh)[68] = (float (*)[68])(smem + 3 * 16 * 68);

    const int m0 = ny * 64;
    const int n0 = nx * 64;
    const int kbase = z * 128;
    const int tx = tid & 15;        // n / 4
    const int ty = tid >> 4;        // m / 8  (0..7)

    float acc[32];
#pragma unroll
    for (int i = 0; i < 32; i++) acc[i] = 0.f;

    const float* Wx = (g == 0) ? Wxf : (g == 1) ? Wxi : (g == 2) ? Wxo : Wxc;
    const float* Wh = (g == 0) ? Whf : (g == 1) ? Whi : (g == 2) ? Who : w;

    const int lk = tid & 15, lr = tid >> 4;        // loader coords

    for (int kc = 0; kc < 128; kc += 16) {
        const int kk0 = kbase + kc;
        // load 64 rows x 16 k for each of x, h0, Wx (+Wh), 8 rows per thread-group
#pragma unroll
        for (int i = 0; i < 8; i++) {
            const int r = i * 8 + lr;              // 0..63
            sAx[lk][r] = x [(m0 + r) * Isz + kk0 + lk];
            sAh[lk][r] = h0[(m0 + r) * Hsz + kk0 + lk];
            sBx[lk][r] = Wx[(n0 + r) * Hsz + kk0 + lk];
        }
        if (g < 3) {
#pragma unroll
            for (int i = 0; i < 8; i++) {
                const int r = i * 8 + lr;
                sBh[lk][r] = Wh[(n0 + r) * Hsz + kk0 + lk];
            }
        } else {
            // plastic w accessed transposed: B[kk][n] = w[kk0+kk][n0+n]
            const int ln = tid & 63, lz = tid >> 6; // lz 0..1
#pragma unroll
            for (int i = 0; i < 8; i++) {
                const int kk = i * 2 + lz;          // 0..15
                sBh[kk][ln] = Wh[(kk0 + kk) * Hsz + n0 + ln];
            }
        }
        __syncthreads();

#pragma unroll
        for (int kk = 0; kk < 16; kk++) {
            const float4 ax0 = *(const float4*)&sAx[kk][ty * 8];
            const float4 ax1 = *(const float4*)&sAx[kk][ty * 8 + 4];
            const float4 ah0 = *(const float4*)&sAh[kk][ty * 8];
            const float4 ah1 = *(const float4*)&sAh[kk][ty * 8 + 4];
            const float4 bx4 = *(const float4*)&sBx[kk][tx * 4];
            const float4 bh4 = *(const float4*)&sBh[kk][tx * 4];
            const float ax[8] = {ax0.x, ax0.y, ax0.z, ax0.w, ax1.x, ax1.y, ax1.z, ax1.w};
            const float ah[8] = {ah0.x, ah0.y, ah0.z, ah0.w, ah1.x, ah1.y, ah1.z, ah1.w};
            const float bx[4] = {bx4.x, bx4.y, bx4.z, bx4.w};
            const float bh[4] = {bh4.x, bh4.y, bh4.z, bh4.w};
#pragma unroll
            for (int mi = 0; mi < 8; mi++)
#pragma unroll
                for (int ni = 0; ni < 4; ni++)
                    acc[mi * 4 + ni] += ax[mi] * bx[ni] + ah[mi] * bh[ni];
        }
        __syncthreads();
    }

#pragma unroll
    for (int mi = 0; mi < 8; mi++) {
        const int m = m0 + ty * 8 + mi, n = n0 + tx * 4;
        float4 v = {acc[mi * 4 + 0], acc[mi * 4 + 1], acc[mi * 4 + 2], acc[mi * 4 + 3]};
        *(float4*)&g_partial[(((z * 4 + g) * Bsz) + m) * Hsz + n] = v;
    }
}

// ---------------------------------------------------------------------------
// Kernel 2: combine partials, gate nonlinearities, cell/hactiv outputs,
// inputstocell scratch, and block-wide reduction for the neuromodulator eta.
// grid 256 (one block per batch row), 512 threads (one per k).
// ---------------------------------------------------------------------------
__global__ __launch_bounds__(512) void combine(
    const float* __restrict__ c0, const float* __restrict__ alpha,
    const float* __restrict__ bxf, const float* __restrict__ bhf,
    const float* __restrict__ bxi, const float* __restrict__ bhi,
    const float* __restrict__ bxo, const float* __restrict__ bho,
    const float* __restrict__ bxc,
    const float* __restrict__ Wmod, const float* __restrict__ bmod,
    float* __restrict__ out_h, float* __restrict__ out_c)
{
    const int b = blockIdx.x, k = threadIdx.x;

    float p[4];
#pragma unroll
    for (int g = 0; g < 4; g++) {
        float s = 0.f;
#pragma unroll
        for (int z = 0; z < 4; z++) s += g_partial[(((z * 4 + g) * Bsz) + b) * Hsz + k];
        p[g] = s;
    }
    float hbs = 0.f;
#pragma unroll
    for (int z = 0; z < 4; z++) hbs += g_hbp[(z * Bsz + b) * Hsz + k];

    const float fgt = 1.f / (1.f + expf(-(p[0] + bxf[k] + bhf[k])));
    const float ipt = 1.f / (1.f + expf(-(p[1] + bxi[k] + bhi[k])));
    const float opt = 1.f / (1.f + expf(-(p[2] + bxo[k] + bho[k])));
    const float itc = tanhf(p[3] + bxc[k] + alpha[k] * hbs);
    const float cell = fgt * c0[b * Hsz + k] + ipt * itc;
    const float hact = opt * tanhf(cell);

    out_h[b * Hsz + k] = hact;
    out_c[b * Hsz + k] = cell;
    g_itc[b * Hsz + k] = itc;

    // eta[b] = tanh( sum_k hact*Wmod[k] + bmod )
    float v = hact * Wmod[k];
#pragma unroll
    for (int off = 16; off; off >>= 1) v += __shfl_xor_sync(0xffffffffu, v, off);
    __shared__ float sred[16];
    const int lane = k & 31, wid = k >> 5;
    if (lane == 0) sred[wid] = v;
    __syncthreads();
    if (wid == 0) {
        float t = (lane < 16) ? sred[lane] : 0.f;
#pragma unroll
        for (int off = 8; off; off >>= 1) t += __shfl_xor_sync(0xffffffffu, t, off);
        if (lane == 0) g_eta[b] = tanhf(t + bmod[0]);
    }
}

// ---------------------------------------------------------------------------
// Kernel 3: Hebbian trace update (268 MB read + 268 MB write, pure stream).
//   hebb_new[b,h,k] = clip(hebb[b,h,k] + (eta[b]*Wfan[k]+bfan[k])*itc[b,k] * h0[b,h], +-2)
// grid (16, 256): 32 h-rows per block, 128 threads x float4 over k.
// ---------------------------------------------------------------------------
__global__ __launch_bounds__(128) void hebbupd(
    const float* __restrict__ h0, const float* __restrict__ hebb,
    const float* __restrict__ Wfan, const float* __restrict__ bfan,
    float* __restrict__ out_hebb)
{
    const int b = blockIdx.y, hb0 = blockIdx.x * 32, t = threadIdx.x;
    __shared__ float4 s[128];
    __shared__ float sh0[32];

    const float eta = g_eta[b];
    {
        const int k = t * 4;
        const float4 it = *(const float4*)&g_itc[b * Hsz + k];
        float4 sv;
        sv.x = (eta * Wfan[k + 0] + bfan[k + 0]) * it.x;
        sv.y = (eta * Wfan[k + 1] + bfan[k + 1]) * it.y;
        sv.z = (eta * Wfan[k + 2] + bfan[k + 2]) * it.z;
        sv.w = (eta * Wfan[k + 3] + bfan[k + 3]) * it.w;
        s[t] = sv;
    }
    if (t < 32) sh0[t] = h0[b * Hsz + hb0 + t];
    __syncthreads();

    const float4 sk = s[t];
    const float4* hp = (const float4*)(hebb + (size_t)b * Hsz * Hsz + (size_t)hb0 * Hsz) + t;
    float4* op = (float4*)(out_hebb + (size_t)b * Hsz * Hsz + (size_t)hb0 * Hsz) + t;
#pragma unroll 8
    for (int hh = 0; hh < 32; hh++) {
        float4 v = __ldcs(&hp[(size_t)hh * 128]);
        const float hv = sh0[hh];
        v.x = fminf(fmaxf(v.x + hv * sk.x, -2.f), 2.f);
        v.y = fminf(fmaxf(v.y + hv * sk.y, -2.f), 2.f);
        v.z = fminf(fmaxf(v.z + hv * sk.z, -2.f), 2.f);
        v.w = fminf(fmaxf(v.w + hv * sk.w, -2.f), 2.f);
        __stcs(&op[(size_t)hh * 128], v);
    }
}

// ---------------------------------------------------------------------------
extern "C" void kernel_launch(void* const* d_in, const int* in_sizes, int n_in,
                              void* d_out, int out_size)
{
    const float* x     = (const float*)d_in[0];
    const float* h0    = (const float*)d_in[1];
    const float* c0    = (const float*)d_in[2];
    const float* hebb  = (const float*)d_in[3];
    const float* w     = (const float*)d_in[4];
    const float* alpha = (const float*)d_in[5];
    const float* Wxf   = (const float*)d_in[6];
    const float* bxf   = (const float*)d_in[7];
    const float* Whf   = (const float*)d_in[8];
    const float* bhf   = (const float*)d_in[9];
    const float* Wxi   = (const float*)d_in[10];
    const float* bxi   = (const float*)d_in[11];
    const float* Whi   = (const float*)d_in[12];
    const float* bhi   = (const float*)d_in[13];
    const float* Wxo   = (const float*)d_in[14];
    const float* bxo   = (const float*)d_in[15];
    const float* Who   = (const float*)d_in[16];
    const float* bho   = (const float*)d_in[17];
    const float* Wxc   = (const float*)d_in[18];
    const float* bxc   = (const float*)d_in[19];
    const float* Wmod  = (const float*)d_in[20];
    const float* bmod  = (const float*)d_in[21];
    const float* Wfan  = (const float*)d_in[22];
    const float* bfan  = (const float*)d_in[23];

    float* out = (float*)d_out;
    float* out_h    = out;                     // hactiv [256,512]
    float* out_c    = out + Bsz * Hsz;         // cell   [256,512]
    float* out_hebb = out + 2 * Bsz * Hsz;     // hebb_new [256,512,512]

    fused_gemm_hebbdot<<<GRID_FUSED, 128>>>(x, h0, Wxf, Wxi, Wxo, Wxc,
                                            Whf, Whi, Who, w, hebb);
    combine<<<256, 512>>>(c0, alpha, bxf, bhf, bxi, bhi, bxo, bho, bxc, Wmod, bmod,
                          out_h, out_c);
    hebbupd<<<dim3(16, 256), 128>>>(h0, hebb, Wfan, bfan, out_hebb);
}